// round 10
// baseline (speedup 1.0000x reference)
#include <cuda_runtime.h>
#include <math.h>
#include <stdint.h>

#define DIMC    768
#define HIDDENC 3072
#define SEQ     1024
#define BATCH   16
#define NTOK    (BATCH*SEQ)   // 16384
#define HEADSC  12
#define HDIM    64
#define QKVN    (3*DIMC)      // 2304
#define LN_EPS  1e-5f

// ---------------- scratch (static device arrays; no allocation allowed) ----------------
__device__ float g_h   [NTOK*DIMC];
__device__ float g_qkv [NTOK*QKVN];
__device__ float g_ctx [NTOK*DIMC];
__device__ float g_x1  [NTOK*DIMC];
__device__ float g_h2  [NTOK*DIMC];
__device__ float g_ffn [NTOK*HIDDENC];
// pre-rounded (tf32) weights, [K][N] row-major
__device__ float g_wqkv[DIMC*QKVN];
__device__ float g_bqkv[QKVN];
__device__ float g_wo  [DIMC*DIMC];
__device__ float g_w1  [DIMC*HIDDENC];
__device__ float g_w2  [HIDDENC*DIMC];

// ---------------- helpers ----------------
__device__ __forceinline__ float tf32r(float x) {
    uint32_t u;
    asm("cvt.rna.tf32.f32 %0, %1;" : "=r"(u) : "f"(x));
    return __uint_as_float(u);
}

__device__ __forceinline__ void mma_m16n8k8(float d[4], const uint32_t a[4], const uint32_t b[2]) {
    asm volatile(
        "mma.sync.aligned.m16n8k8.row.col.f32.tf32.tf32.f32 "
        "{%0,%1,%2,%3}, {%4,%5,%6,%7}, {%8,%9}, {%0,%1,%2,%3};"
        : "+f"(d[0]), "+f"(d[1]), "+f"(d[2]), "+f"(d[3])
        : "r"(a[0]), "r"(a[1]), "r"(a[2]), "r"(a[3]), "r"(b[0]), "r"(b[1]));
}

__device__ __forceinline__ void cp_async16(void* smem, const void* gmem) {
    uint32_t s = (uint32_t)__cvta_generic_to_shared(smem);
    asm volatile("cp.async.cg.shared.global [%0], [%1], 16;" :: "r"(s), "l"(gmem));
}

// ---------------- weight prep ----------------------------------------------------------
__global__ __launch_bounds__(256) void pack_qkv_w(
    const float* __restrict__ Wq, const float* __restrict__ Wk,
    const float* __restrict__ Wv, float* __restrict__ out)
{
    int idx = blockIdx.x * 256 + threadIdx.x;
    if (idx >= DIMC * QKVN) return;
    int k = idx / QKVN, j = idx % QKVN;
    float v = (j < DIMC) ? Wq[k * DIMC + j]
            : (j < 2 * DIMC) ? Wk[k * DIMC + j - DIMC]
            : Wv[k * DIMC + j - 2 * DIMC];
    out[idx] = tf32r(v);
}

__global__ void pack_qkv_b(const float* __restrict__ bq, const float* __restrict__ bk,
                           const float* __restrict__ bv, float* __restrict__ out)
{
    int j = blockIdx.x * 256 + threadIdx.x;
    if (j >= QKVN) return;
    out[j] = (j < DIMC) ? bq[j] : (j < 2 * DIMC) ? bk[j - DIMC] : bv[j - 2 * DIMC];
}

__global__ __launch_bounds__(256) void round_mat(const float* __restrict__ in,
                                                 float* __restrict__ out, int n)
{
    int i = blockIdx.x * 256 + threadIdx.x;
    if (i < n) out[i] = tf32r(in[i]);
}

// ---------------- LayerNorm (tf32-rounded output) --------------------------------------
__global__ __launch_bounds__(256) void ln_kernel(
    const float* __restrict__ x, const float* __restrict__ g,
    const float* __restrict__ b, float* __restrict__ out)
{
    const int row = blockIdx.x;
    const int t = threadIdx.x;
    const float* xr = x + (size_t)row * DIMC;
    float v0 = xr[t], v1 = xr[t + 256], v2 = xr[t + 512];
    float s  = v0 + v1 + v2;
    float ss = v0*v0 + v1*v1 + v2*v2;
    #pragma unroll
    for (int o = 16; o; o >>= 1) {
        s  += __shfl_xor_sync(0xffffffffu, s,  o);
        ss += __shfl_xor_sync(0xffffffffu, ss, o);
    }
    __shared__ float sm[8], sm2[8];
    const int w = t >> 5, l = t & 31;
    if (l == 0) { sm[w] = s; sm2[w] = ss; }
    __syncthreads();
    if (w == 0) {
        s  = (l < 8) ? sm[l]  : 0.f;
        ss = (l < 8) ? sm2[l] : 0.f;
        #pragma unroll
        for (int o = 4; o; o >>= 1) {
            s  += __shfl_xor_sync(0xffffffffu, s,  o);
            ss += __shfl_xor_sync(0xffffffffu, ss, o);
        }
        if (l == 0) {
            float mu = s * (1.f / DIMC);
            sm[0]  = mu;
            sm2[0] = rsqrtf(ss * (1.f / DIMC) - mu * mu + LN_EPS);
        }
    }
    __syncthreads();
    const float mu = sm[0], rstd = sm2[0];
    float* orow = out + (size_t)row * DIMC;
    orow[t]       = tf32r((v0 - mu) * rstd * g[t]       + b[t]);
    orow[t + 256] = tf32r((v1 - mu) * rstd * g[t + 256] + b[t + 256]);
    orow[t + 512] = tf32r((v2 - mu) * rstd * g[t + 512] + b[t + 512]);
}

// ---------------- TF32 tensor-core GEMM, 3-stage pipeline ------------------------------
// Iteration order (CUTLASS multistage): wait_group -> __syncthreads -> issue -> compute.
// RAW: tile kt complete in ALL threads after the barrier. WAR: stage overwritten at kt
// was computed at kt-1, all threads passed the barrier after it.
#define AS_STRIDE 36
#define BS_STRIDE 136
#define A_TILE (128*AS_STRIDE)
#define B_TILE (32*BS_STRIDE)
#define GEMM_SMEM ((3*(A_TILE+B_TILE))*4)   // 107520 bytes

__global__ __launch_bounds__(128) void gemm_tf32(
    const float* __restrict__ A, const float* __restrict__ B,
    const float* __restrict__ bias, const float* __restrict__ res,
    float* __restrict__ C, int M, int N, int K, int do_gelu, int rnd)
{
    extern __shared__ float smem[];
    float* const AsBase = smem;
    float* const BsBase = smem + 3 * A_TILE;

    const int bx = blockIdx.x * 128;
    const int by = blockIdx.y * 128;
    const int tid = threadIdx.x;
    const int wid = tid >> 5;
    const int lane = tid & 31;
    const int g  = lane >> 2;
    const int tg = lane & 3;

    const int wm = (wid & 1) * 64;
    const int wn = (wid >> 1) * 64;

    float acc[4][8][4];
    #pragma unroll
    for (int mt = 0; mt < 4; mt++)
        #pragma unroll
        for (int nt = 0; nt < 8; nt++)
            #pragma unroll
            for (int r = 0; r < 4; r++) acc[mt][nt][r] = 0.f;

    const int KT = K / 32;

    auto load_stage = [&](int stage, int k0) {
        float* As = AsBase + stage * A_TILE;
        float* Bs = BsBase + stage * B_TILE;
        #pragma unroll
        for (int i = 0; i < 8; i++) {
            const int idx  = tid + 128 * i;
            const int arow = idx >> 3, ac4 = (idx & 7) * 4;
            cp_async16(&As[arow * AS_STRIDE + ac4],
                       A + (size_t)(by + arow) * K + k0 + ac4);
            const int brow = idx >> 5, bc4 = (idx & 31) * 4;
            cp_async16(&Bs[brow * BS_STRIDE + bc4],
                       B + (size_t)(k0 + brow) * N + bx + bc4);
        }
        asm volatile("cp.async.commit_group;");
    };

    load_stage(0, 0);
    load_stage(1, 32);

    int s = 0;
    for (int kt = 0; kt < KT; kt++) {
        // pending groups: {kt, kt+1} (or {kt} on the last iteration)
        if (kt + 1 < KT) {
            asm volatile("cp.async.wait_group 1;");
        } else {
            asm volatile("cp.async.wait_group 0;");
        }
        __syncthreads();   // publish tile kt to all threads; all done computing kt-1

        if (kt + 2 < KT) {
            int ns = s + 2; if (ns >= 3) ns -= 3;
            load_stage(ns, (kt + 2) * 32);
        }

        const float* as = AsBase + s * A_TILE;
        const float* bs = BsBase + s * B_TILE;
        #pragma unroll
        for (int kk = 0; kk < 32; kk += 8) {
            uint32_t af[4][4];
            #pragma unroll
            for (int mt = 0; mt < 4; mt++) {
                const int m0 = wm + mt * 16 + g;
                af[mt][0] = __float_as_uint(as[m0 * AS_STRIDE + kk + tg]);
                af[mt][1] = __float_as_uint(as[(m0 + 8) * AS_STRIDE + kk + tg]);
                af[mt][2] = __float_as_uint(as[m0 * AS_STRIDE + kk + tg + 4]);
                af[mt][3] = __float_as_uint(as[(m0 + 8) * AS_STRIDE + kk + tg + 4]);
            }
            uint32_t bf[8][2];
            #pragma unroll
            for (int nt = 0; nt < 8; nt++) {
                const int n0 = wn + nt * 8 + g;
                bf[nt][0] = __float_as_uint(bs[(kk + tg) * BS_STRIDE + n0]);
                bf[nt][1] = __float_as_uint(bs[(kk + tg + 4) * BS_STRIDE + n0]);
            }
            #pragma unroll
            for (int mt = 0; mt < 4; mt++)
                #pragma unroll
                for (int nt = 0; nt < 8; nt++)
                    mma_m16n8k8(acc[mt][nt], af[mt], bf[nt]);
        }
        if (++s >= 3) s -= 3;
    }

    // epilogue
    #pragma unroll
    for (int mt = 0; mt < 4; mt++) {
        const int r0 = by + wm + mt * 16 + g;
        #pragma unroll
        for (int nt = 0; nt < 8; nt++) {
            const int c0 = bx + wn + nt * 8 + tg * 2;
            const float b0 = bias[c0], b1 = bias[c0 + 1];
            float v00 = acc[mt][nt][0] + b0;
            float v01 = acc[mt][nt][1] + b1;
            float v10 = acc[mt][nt][2] + b0;
            float v11 = acc[mt][nt][3] + b1;
            if (do_gelu) {
                v00 = 0.5f * v00 * (1.0f + erff(v00 * 0.70710678118654752f));
                v01 = 0.5f * v01 * (1.0f + erff(v01 * 0.70710678118654752f));
                v10 = 0.5f * v10 * (1.0f + erff(v10 * 0.70710678118654752f));
                v11 = 0.5f * v11 * (1.0f + erff(v11 * 0.70710678118654752f));
            }
            if (res) {
                const float2 r01 = *(const float2*)&res[(size_t)r0 * N + c0];
                const float2 r11 = *(const float2*)&res[(size_t)(r0 + 8) * N + c0];
                v00 += r01.x; v01 += r01.y;
                v10 += r11.x; v11 += r11.y;
            }
            if (rnd) {
                v00 = tf32r(v00); v01 = tf32r(v01);
                v10 = tf32r(v10); v11 = tf32r(v11);
            }
            *(float2*)&C[(size_t)r0 * N + c0]       = make_float2(v00, v01);
            *(float2*)&C[(size_t)(r0 + 8) * N + c0] = make_float2(v10, v11);
        }
    }
}

// ---------------- TF32 flash attention: double-buffered K/V, 1 barrier/iter ------------
// Order per iteration: wait_group 0 -> __syncthreads -> issue load(kt+1) -> compute(kt).
#define KS_STRIDE 68
#define VS_STRIDE 72
#define PS_STRIDE 68
#define KS_TILE (64*KS_STRIDE)
#define VS_TILE (64*VS_STRIDE)
#define ATTN_SMEM ((2*KS_TILE + 2*VS_TILE + 128*PS_STRIDE)*4)   // 106496 bytes

__global__ __launch_bounds__(128) void attn_tc(
    const float* __restrict__ qkv, float* __restrict__ ctx)
{
    extern __shared__ float asmem[];
    float* const KsB = asmem;                       // 2 stages
    float* const VsB = asmem + 2 * KS_TILE;         // 2 stages
    float* const Ps  = asmem + 2 * KS_TILE + 2 * VS_TILE;   // 128 x PS_STRIDE

    const int qt = blockIdx.x, h = blockIdx.y, b = blockIdx.z;
    const int tid = threadIdx.x, w = tid >> 5, lane = tid & 31;
    const int g = lane >> 2, tg = lane & 3;

    const int qrow0 = b * SEQ + qt * 128 + w * 32;
    const float* qbase = qkv + (size_t)qrow0 * QKVN + h * HDIM;

    uint32_t af[2][8][4];
    #pragma unroll
    for (int mt = 0; mt < 2; mt++)
        #pragma unroll
        for (int c = 0; c < 8; c++) {
            const int r0 = mt * 16 + g;
            af[mt][c][0] = __float_as_uint(0.125f * qbase[(size_t)r0       * QKVN + c * 8 + tg]);
            af[mt][c][1] = __float_as_uint(0.125f * qbase[(size_t)(r0 + 8) * QKVN + c * 8 + tg]);
            af[mt][c][2] = __float_as_uint(0.125f * qbase[(size_t)r0       * QKVN + c * 8 + tg + 4]);
            af[mt][c][3] = __float_as_uint(0.125f * qbase[(size_t)(r0 + 8) * QKVN + c * 8 + tg + 4]);
        }

    float o[2][8][4];
    #pragma unroll
    for (int mt = 0; mt < 2; mt++)
        #pragma unroll
        for (int nt = 0; nt < 8; nt++)
            #pragma unroll
            for (int r = 0; r < 4; r++) o[mt][nt][r] = 0.f;
    float mst[2][2] = {{-1e30f, -1e30f}, {-1e30f, -1e30f}};
    float lst[2][2] = {{0.f, 0.f}, {0.f, 0.f}};

    auto load_kv = [&](int st, int kt) {
        const float* kb = qkv + (size_t)(b * SEQ + kt * 64) * QKVN + DIMC + h * HDIM;
        const float* vb = kb + DIMC;
        float* Kst = KsB + st * KS_TILE;
        float* Vst = VsB + st * VS_TILE;
        #pragma unroll
        for (int it = 0; it < 8; it++) {
            int e4  = it * 128 + tid;
            int row = e4 >> 4;
            int d4  = (e4 & 15) * 4;
            cp_async16(&Kst[row * KS_STRIDE + d4], kb + (size_t)row * QKVN + d4);
            cp_async16(&Vst[row * VS_STRIDE + d4], vb + (size_t)row * QKVN + d4);
        }
        asm volatile("cp.async.commit_group;");
    };

    load_kv(0, 0);

    const int NKT = SEQ / 64;
    for (int kt = 0; kt < NKT; kt++) {
        const int s = kt & 1;
        asm volatile("cp.async.wait_group 0;");   // own copies of tile kt done
        __syncthreads();                          // publish to all threads; kt-1 compute done
        if (kt + 1 < NKT) load_kv(s ^ 1, kt + 1); // overlaps compute below

        const float* Kst = KsB + s * KS_TILE;
        const float* Vst = VsB + s * VS_TILE;

        // S = (Q*scale) @ K^T; K fragments shared across both m-tiles
        float sc[2][8][4];
        #pragma unroll
        for (int mt = 0; mt < 2; mt++)
            #pragma unroll
            for (int nt = 0; nt < 8; nt++)
                #pragma unroll
                for (int r = 0; r < 4; r++) sc[mt][nt][r] = 0.f;
        #pragma unroll
        for (int c = 0; c < 8; c++) {
            #pragma unroll
            for (int nt = 0; nt < 8; nt++) {
                uint32_t bf[2];
                bf[0] = __float_as_uint(Kst[(nt * 8 + g) * KS_STRIDE + c * 8 + tg]);
                bf[1] = __float_as_uint(Kst[(nt * 8 + g) * KS_STRIDE + c * 8 + tg + 4]);
                mma_m16n8k8(sc[0][nt], af[0][c], bf);
                mma_m16n8k8(sc[1][nt], af[1][c], bf);
            }
        }

        // online softmax per m-tile + P staging
        #pragma unroll
        for (int mt = 0; mt < 2; mt++) {
            float tm0 = -1e30f, tm1 = -1e30f;
            #pragma unroll
            for (int nt = 0; nt < 8; nt++) {
                tm0 = fmaxf(tm0, fmaxf(sc[mt][nt][0], sc[mt][nt][1]));
                tm1 = fmaxf(tm1, fmaxf(sc[mt][nt][2], sc[mt][nt][3]));
            }
            tm0 = fmaxf(tm0, __shfl_xor_sync(0xffffffffu, tm0, 1));
            tm0 = fmaxf(tm0, __shfl_xor_sync(0xffffffffu, tm0, 2));
            tm1 = fmaxf(tm1, __shfl_xor_sync(0xffffffffu, tm1, 1));
            tm1 = fmaxf(tm1, __shfl_xor_sync(0xffffffffu, tm1, 2));
            const float mn0 = fmaxf(mst[mt][0], tm0), mn1 = fmaxf(mst[mt][1], tm1);
            const float a0 = __expf(mst[mt][0] - mn0), a1 = __expf(mst[mt][1] - mn1);
            mst[mt][0] = mn0; mst[mt][1] = mn1;

            float rs0 = 0.f, rs1 = 0.f;
            #pragma unroll
            for (int nt = 0; nt < 8; nt++) {
                sc[mt][nt][0] = __expf(sc[mt][nt][0] - mn0);
                sc[mt][nt][1] = __expf(sc[mt][nt][1] - mn0);
                sc[mt][nt][2] = __expf(sc[mt][nt][2] - mn1);
                sc[mt][nt][3] = __expf(sc[mt][nt][3] - mn1);
                rs0 += sc[mt][nt][0] + sc[mt][nt][1];
                rs1 += sc[mt][nt][2] + sc[mt][nt][3];
            }
            rs0 += __shfl_xor_sync(0xffffffffu, rs0, 1);
            rs0 += __shfl_xor_sync(0xffffffffu, rs0, 2);
            rs1 += __shfl_xor_sync(0xffffffffu, rs1, 1);
            rs1 += __shfl_xor_sync(0xffffffffu, rs1, 2);
            lst[mt][0] = lst[mt][0] * a0 + rs0;
            lst[mt][1] = lst[mt][1] * a1 + rs1;

            #pragma unroll
            for (int nt = 0; nt < 8; nt++) {
                o[mt][nt][0] *= a0; o[mt][nt][1] *= a0;
                o[mt][nt][2] *= a1; o[mt][nt][3] *= a1;
            }

            const int pr = w * 32 + mt * 16;
            #pragma unroll
            for (int nt = 0; nt < 8; nt++) {
                *(float2*)&Ps[(pr + g) * PS_STRIDE + nt * 8 + 2 * tg] =
                    make_float2(tf32r(sc[mt][nt][0]), tf32r(sc[mt][nt][1]));
                *(float2*)&Ps[(pr + g + 8) * PS_STRIDE + nt * 8 + 2 * tg] =
                    make_float2(tf32r(sc[mt][nt][2]), tf32r(sc[mt][nt][3]));
            }
        }
        __syncwarp();

        // O += P @ V, V fragments reused across both m-tiles
        const int pr = w * 32;
        #pragma unroll
        for (int c = 0; c < 8; c++) {
            uint32_t pa0[4], pa1[4];
            pa0[0] = __float_as_uint(Ps[(pr + g)      * PS_STRIDE + c * 8 + tg]);
            pa0[1] = __float_as_uint(Ps[(pr + g + 8)  * PS_STRIDE + c * 8 + tg]);
            pa0[2] = __float_as_uint(Ps[(pr + g)      * PS_STRIDE + c * 8 + tg + 4]);
            pa0[3] = __float_as_uint(Ps[(pr + g + 8)  * PS_STRIDE + c * 8 + tg + 4]);
            pa1[0] = __float_as_uint(Ps[(pr + 16 + g)     * PS_STRIDE + c * 8 + tg]);
            pa1[1] = __float_as_uint(Ps[(pr + 16 + g + 8) * PS_STRIDE + c * 8 + tg]);
            pa1[2] = __float_as_uint(Ps[(pr + 16 + g)     * PS_STRIDE + c * 8 + tg + 4]);
            pa1[3] = __float_as_uint(Ps[(pr + 16 + g + 8) * PS_STRIDE + c * 8 + tg + 4]);
            #pragma unroll
            for (int nt = 0; nt < 8; nt++) {
                uint32_t vbf[2];
                vbf[0] = __float_as_uint(Vst[(c * 8 + tg)     * VS_STRIDE + nt * 8 + g]);
                vbf[1] = __float_as_uint(Vst[(c * 8 + tg + 4) * VS_STRIDE + nt * 8 + g]);
                mma_m16n8k8(o[0][nt], pa0, vbf);
                mma_m16n8k8(o[1][nt], pa1, vbf);
            }
        }
    }

    #pragma unroll
    for (int mt = 0; mt < 2; mt++) {
        const float inv0 = 1.f / lst[mt][0], inv1 = 1.f / lst[mt][1];
        float* c0p = ctx + (size_t)(qrow0 + mt * 16 + g)     * DIMC + h * HDIM;
        float* c1p = ctx + (size_t)(qrow0 + mt * 16 + g + 8) * DIMC + h * HDIM;
        #pragma unroll
        for (int nt = 0; nt < 8; nt++) {
            *(float2*)&c0p[nt * 8 + 2 * tg] = make_float2(tf32r(o[mt][nt][0] * inv0), tf32r(o[mt][nt][1] * inv0));
            *(float2*)&c1p[nt * 8 + 2 * tg] = make_float2(tf32r(o[mt][nt][2] * inv1), tf32r(o[mt][nt][3] * inv1));
        }
    }
}

// ---------------- launch ----------------
extern "C" void kernel_launch(void* const* d_in, const int* in_sizes, int n_in,
                              void* d_out, int out_size)
{
    const float* x    = (const float*)d_in[0];
    const float* ln1g = (const float*)d_in[1];
    const float* ln1b = (const float*)d_in[2];
    const float* Wq   = (const float*)d_in[3];
    const float* bq   = (const float*)d_in[4];
    const float* Wk   = (const float*)d_in[5];
    const float* bk   = (const float*)d_in[6];
    const float* Wv   = (const float*)d_in[7];
    const float* bv   = (const float*)d_in[8];
    const float* Wo   = (const float*)d_in[9];
    const float* bo   = (const float*)d_in[10];
    const float* ln2g = (const float*)d_in[11];
    const float* ln2b = (const float*)d_in[12];
    const float* W1   = (const float*)d_in[13];
    const float* b1   = (const float*)d_in[14];
    const float* W2   = (const float*)d_in[15];
    const float* b2   = (const float*)d_in[16];
    float* out = (float*)d_out;

    float *h, *qkv, *ctx, *x1, *h2, *ffn;
    float *wqkv, *bqkv, *wo, *w1, *w2;
    cudaGetSymbolAddress((void**)&h,    g_h);
    cudaGetSymbolAddress((void**)&qkv,  g_qkv);
    cudaGetSymbolAddress((void**)&ctx,  g_ctx);
    cudaGetSymbolAddress((void**)&x1,   g_x1);
    cudaGetSymbolAddress((void**)&h2,   g_h2);
    cudaGetSymbolAddress((void**)&ffn,  g_ffn);
    cudaGetSymbolAddress((void**)&wqkv, g_wqkv);
    cudaGetSymbolAddress((void**)&bqkv, g_bqkv);
    cudaGetSymbolAddress((void**)&wo,   g_wo);
    cudaGetSymbolAddress((void**)&w1,   g_w1);
    cudaGetSymbolAddress((void**)&w2,   g_w2);

    cudaFuncSetAttribute(gemm_tf32, cudaFuncAttributeMaxDynamicSharedMemorySize, GEMM_SMEM);
    cudaFuncSetAttribute(attn_tc,  cudaFuncAttributeMaxDynamicSharedMemorySize, ATTN_SMEM);

    const dim3 blk(256);
    const dim3 gblk(128);

    // weight prep (rounded to tf32 grid once per launch)
    pack_qkv_w<<<(DIMC * QKVN + 255) / 256, blk>>>(Wq, Wk, Wv, wqkv);
    pack_qkv_b<<<(QKVN + 255) / 256, blk>>>(bq, bk, bv, bqkv);
    round_mat<<<(DIMC * DIMC + 255) / 256, blk>>>(Wo, wo, DIMC * DIMC);
    round_mat<<<(DIMC * HIDDENC + 255) / 256, blk>>>(W1, w1, DIMC * HIDDENC);
    round_mat<<<(HIDDENC * DIMC + 255) / 256, blk>>>(W2, w2, HIDDENC * DIMC);

    const dim3 gqkv(QKVN / 128, NTOK / 128);     // 18 x 128
    const dim3 gd(DIMC / 128, NTOK / 128);       // 6 x 128
    const dim3 gh(HIDDENC / 128, NTOK / 128);    // 24 x 128

    // 1) LN1 (rounded out)
    ln_kernel<<<NTOK, blk>>>(x, ln1g, ln1b, h);
    // 2) fused QKV projection (rounded out)
    gemm_tf32<<<gqkv, gblk, GEMM_SMEM>>>(h, wqkv, bqkv, nullptr, qkv, NTOK, QKVN, DIMC, 0, 1);
    // 3) flash attention, 128 q-rows/block (rounded out)
    attn_tc<<<dim3(SEQ / 128, HEADSC, BATCH), 128, ATTN_SMEM>>>(qkv, ctx);
    // 4) x1 = x + ctx@Wo + bo (full fp32 out)
    gemm_tf32<<<gd, gblk, GEMM_SMEM>>>(ctx, wo, bo, x, x1, NTOK, DIMC, DIMC, 0, 0);
    // 5) LN2 (rounded out)
    ln_kernel<<<NTOK, blk>>>(x1, ln2g, ln2b, h2);
    // 6) FFN up + exact GELU (rounded out)
    gemm_tf32<<<gh, gblk, GEMM_SMEM>>>(h2, w1, b1, nullptr, ffn, NTOK, HIDDENC, DIMC, 1, 1);
    // 7) out = x1 + ffn@W2 + b2 (full fp32 out)
    gemm_tf32<<<gd, gblk, GEMM_SMEM>>>(ffn, w2, b2, x1, out, NTOK, DIMC, HIDDENC, 0, 0);
}